// round 14
// baseline (speedup 1.0000x reference)
#include <cuda_runtime.h>

#define B_    8
#define N_    1024
#define DIM_  256
#define H_    4
#define DH_   32
#define HID_  128
#define QKV_  384
#define INDC_ 5
#define SCALE_ 0.17677669529663687f
#define EPS_  1e-5f
#define SLAB_ (B_*HID_*N_)

// ---------------- scratch ----------------
__device__ float g_qkv[B_*QKV_*N_];   // q raw, k softmaxed in place, v raw
__device__ float g_KV [B_*H_*DH_*DH_];// KV[b][h][e][d] (atomic accum; zeroed by kK)
__device__ float g_o2 [4*SLAB_];      // indicator-term partials, one slab per j-chunk
__device__ float g_lin[SLAB_];        // linear-term output

__device__ __forceinline__ unsigned tf32u(float f) {
    unsigned u; asm("cvt.rna.tf32.f32 %0, %1;" : "=r"(u) : "f"(f)); return u;
}
__device__ __forceinline__ uint2 split_tf32(float v) {
    unsigned hi = tf32u(v);
    float r = v - __uint_as_float(hi);
    return make_uint2(hi, tf32u(r));
}
__device__ __forceinline__ void mma8(float* c,
                                     unsigned a0, unsigned a1, unsigned a2, unsigned a3,
                                     unsigned b0, unsigned b1) {
    asm volatile("mma.sync.aligned.m16n8k8.row.col.f32.tf32.tf32.f32 "
                 "{%0,%1,%2,%3}, {%4,%5,%6,%7}, {%8,%9}, {%0,%1,%2,%3};\n"
                 : "+f"(c[0]), "+f"(c[1]), "+f"(c[2]), "+f"(c[3])
                 : "r"(a0), "r"(a1), "r"(a2), "r"(a3), "r"(b0), "r"(b1));
}
__device__ __forceinline__ void cpa16(void* dst, const void* src) {
    unsigned d = (unsigned)__cvta_generic_to_shared(dst);
    asm volatile("cp.async.ca.shared.global [%0], [%1], 16;\n" :: "r"(d), "l"(src));
}

// =================================================================
// Kernel A (tf32 2-MMA): qkv[b] = W_qkv @ x[b];  D = Wh*xh + Wh*xl
// =================================================================
__global__ void __launch_bounds__(256) kA(const float* __restrict__ W,
                                          const float* __restrict__ x) {
    int i0 = blockIdx.x * 64, o0 = blockIdx.y * 128, b = blockIdx.z;
    __shared__ unsigned A_s[16][136];
    __shared__ unsigned B_s[16][68][2];
    int t = threadIdx.x, warp = t >> 5, lane = t & 31;
    int g = lane >> 2, tig = lane & 3;
    int wm = warp >> 1, wn = warp & 1;
    const float* xb = x + (long)b * DIM_ * N_;

    int aq = t & 3, am = t >> 2;
    int bq = t & 15, bk = t >> 4;

    float4 pa[2], pb;
    #pragma unroll
    for (int r = 0; r < 2; r++)
        pa[r] = *(const float4*)(W + (o0 + am + 64*r) * DIM_ + aq*4);
    pb = *(const float4*)(xb + bk * N_ + i0 + bq*4);

    float acc[2][4][4];
    #pragma unroll
    for (int mt = 0; mt < 2; mt++)
        #pragma unroll
        for (int nt = 0; nt < 4; nt++)
            #pragma unroll
            for (int z = 0; z < 4; z++) acc[mt][nt][z] = 0.f;

    for (int c = 0; c < 16; c++) {
        if (c) __syncthreads();
        #pragma unroll
        for (int r = 0; r < 2; r++) {
            const float* pv = (const float*)&pa[r];
            #pragma unroll
            for (int j = 0; j < 4; j++)
                A_s[aq*4+j][am + 64*r] = tf32u(pv[j]);
        }
        {
            const float* pv = (const float*)&pb;
            #pragma unroll
            for (int j = 0; j < 4; j++)
                *(uint2*)&B_s[bk][bq*4+j][0] = split_tf32(pv[j]);
        }
        if (c + 1 < 16) {
            int k0n = (c + 1) * 16;
            #pragma unroll
            for (int r = 0; r < 2; r++)
                pa[r] = *(const float4*)(W + (o0 + am + 64*r) * DIM_ + k0n + aq*4);
            pb = *(const float4*)(xb + (k0n + bk) * N_ + i0 + bq*4);
        }
        __syncthreads();
        #pragma unroll
        for (int ks = 0; ks < 2; ks++) {
            int k8 = ks * 8;
            uint2 Bf[4][2];
            #pragma unroll
            for (int nt = 0; nt < 4; nt++) {
                int cn = wn*32 + nt*8 + g;
                Bf[nt][0] = *(uint2*)&B_s[k8 + tig    ][cn][0];
                Bf[nt][1] = *(uint2*)&B_s[k8 + tig + 4][cn][0];
            }
            #pragma unroll
            for (int mt = 0; mt < 2; mt++) {
                int rm = wm*32 + mt*16 + g;
                unsigned A0 = A_s[k8 + tig    ][rm    ];
                unsigned A1 = A_s[k8 + tig    ][rm + 8];
                unsigned A2 = A_s[k8 + tig + 4][rm    ];
                unsigned A3 = A_s[k8 + tig + 4][rm + 8];
                #pragma unroll
                for (int nt = 0; nt < 4; nt++) {
                    mma8(acc[mt][nt], A0, A1, A2, A3, Bf[nt][0].x, Bf[nt][1].x);
                    mma8(acc[mt][nt], A0, A1, A2, A3, Bf[nt][0].y, Bf[nt][1].y);
                }
            }
        }
    }
    #pragma unroll
    for (int mt = 0; mt < 2; mt++) {
        int row = o0 + wm*32 + mt*16 + g;
        #pragma unroll
        for (int nt = 0; nt < 4; nt++) {
            int col = i0 + wn*32 + nt*8 + tig*2;
            *(float2*)(g_qkv + ((long)b*QKV_ + row    ) * N_ + col) =
                make_float2(acc[mt][nt][0], acc[mt][nt][1]);
            *(float2*)(g_qkv + ((long)b*QKV_ + row + 8) * N_ + col) =
                make_float2(acc[mt][nt][2], acc[mt][nt][3]);
        }
    }
}

// =================================================================
// Kernel K: softmax over n (1024) of each k row, in place.
// Also zeroes g_KV (blocks with row<4; done before kKV runs).
// =================================================================
__global__ void __launch_bounds__(256) kK() {
    int row = blockIdx.x, b = blockIdx.y;
    int t = threadIdx.x;
    if (row < 4) {
        float4 z = make_float4(0.f, 0.f, 0.f, 0.f);
        *(float4*)(g_KV + ((long)(b*4 + row) << 10) + t*4) = z;
    }
    float* p = g_qkv + ((long)b*QKV_ + HID_ + row) * N_;
    __shared__ float red[8];
    float4 v = *(const float4*)(p + t*4);
    float m = fmaxf(fmaxf(v.x, v.y), fmaxf(v.z, v.w));
    #pragma unroll
    for (int o = 16; o; o >>= 1) m = fmaxf(m, __shfl_xor_sync(0xffffffffu, m, o));
    if ((t & 31) == 0) red[t >> 5] = m;
    __syncthreads();
    m = red[0];
    #pragma unroll
    for (int w = 1; w < 8; w++) m = fmaxf(m, red[w]);
    float e0 = __expf(v.x - m), e1 = __expf(v.y - m);
    float e2 = __expf(v.z - m), e3 = __expf(v.w - m);
    float s = e0 + e1 + e2 + e3;
    #pragma unroll
    for (int o = 16; o; o >>= 1) s += __shfl_xor_sync(0xffffffffu, s, o);
    __syncthreads();
    if ((t & 31) == 0) red[t >> 5] = s;
    __syncthreads();
    float tot = 0.f;
    #pragma unroll
    for (int w = 0; w < 8; w++) tot += red[w];
    float inv = 1.f / tot;
    *(float4*)(p + t*4) = make_float4(e0*inv, e1*inv, e2*inv, e3*inv);
}

// =================================================================
// Kernel KV (j-split x8, 4e x 4d tiles): atomic accum into g_KV
// =================================================================
__global__ void __launch_bounds__(256) kKV() {
    int bh = blockIdx.x; int b = bh >> 2, h = bh & 3;
    int jbase = blockIdx.y * 128;
    __shared__ float ksm[32][33], vsm[32][33];
    int t = threadIdx.x;
    int jg = t & 3, dg = (t >> 2) & 7, eg = t >> 5;
    int e0 = eg * 4, d0 = dg * 4;
    float acc[4][4] = {};
    const float* kbase = g_qkv + ((long)b*QKV_ + HID_   + h*DH_) * N_;
    const float* vbase = g_qkv + ((long)b*QKV_ + 2*HID_ + h*DH_) * N_;
    for (int jc = 0; jc < 4; jc++) {
        int j0 = jbase + jc * 32;
        if (jc) __syncthreads();
        {
            int ee = t >> 3, j4 = t & 7;
            float4 kv = *(const float4*)(kbase + ee * N_ + j0 + j4*4);
            ksm[ee][j4*4+0] = kv.x; ksm[ee][j4*4+1] = kv.y;
            ksm[ee][j4*4+2] = kv.z; ksm[ee][j4*4+3] = kv.w;
            float4 vv = *(const float4*)(vbase + ee * N_ + j0 + j4*4);
            vsm[ee][j4*4+0] = vv.x; vsm[ee][j4*4+1] = vv.y;
            vsm[ee][j4*4+2] = vv.z; vsm[ee][j4*4+3] = vv.w;
        }
        __syncthreads();
        #pragma unroll
        for (int i = 0; i < 8; i++) {
            int jj = jg * 8 + ((i + dg) & 7);
            float kr[4], vr[4];
            #pragma unroll
            for (int u = 0; u < 4; u++) kr[u] = ksm[e0+u][jj];
            #pragma unroll
            for (int u = 0; u < 4; u++) vr[u] = vsm[d0+u][jj];
            #pragma unroll
            for (int u = 0; u < 4; u++)
                #pragma unroll
                for (int w2 = 0; w2 < 4; w2++)
                    acc[u][w2] += kr[u] * vr[w2];
        }
    }
    float* dst = g_KV + (long)bh * DH_ * DH_;
    #pragma unroll
    for (int u = 0; u < 4; u++)
        #pragma unroll
        for (int w2 = 0; w2 < 4; w2++)
            atomicAdd(dst + (e0+u)*DH_ + d0 + w2, acc[u][w2]);
}

// =================================================================
// Kernel Lin (fused q-softmax, d-split x2, float4 kv) -> g_lin
// =================================================================
__global__ void __launch_bounds__(128) kLin() {
    int it = blockIdx.x, hy = blockIdx.y, b = blockIdx.z;
    int h = hy >> 1, dh = (hy & 1) * 16;
    int i0 = it * 128, t = threadIdx.x;
    __shared__ float q_s[32][129];
    __shared__ float kv_s[32][20];
    for (int e = 0; e < 32; e++)
        q_s[e][t] = g_qkv[((long)b*QKV_ + h*DH_ + e) * N_ + i0 + t];
    #pragma unroll
    for (int r = 0; r < 4; r++) {
        int idx = t + r * 128;
        int e = idx >> 4, d = idx & 15;
        kv_s[e][d] = g_KV[(((long)(b*H_ + h))*DH_ + e) * DH_ + dh + d];
    }
    __syncthreads();
    float p[32];
    float m = -1e30f;
    #pragma unroll
    for (int e = 0; e < 32; e++) { p[e] = q_s[e][t]; m = fmaxf(m, p[e]); }
    float s = 0.f;
    #pragma unroll
    for (int e = 0; e < 32; e++) { p[e] = __expf(p[e] - m); s += p[e]; }
    float acc[16] = {};
    #pragma unroll 4
    for (int e = 0; e < 32; e++) {
        float pe = p[e];
        float4 k0 = *(float4*)&kv_s[e][0];
        float4 k1 = *(float4*)&kv_s[e][4];
        float4 k2 = *(float4*)&kv_s[e][8];
        float4 k3 = *(float4*)&kv_s[e][12];
        acc[0] += pe*k0.x; acc[1] += pe*k0.y; acc[2]  += pe*k0.z; acc[3]  += pe*k0.w;
        acc[4] += pe*k1.x; acc[5] += pe*k1.y; acc[6]  += pe*k1.z; acc[7]  += pe*k1.w;
        acc[8] += pe*k2.x; acc[9] += pe*k2.y; acc[10] += pe*k2.z; acc[11] += pe*k2.w;
        acc[12]+= pe*k3.x; acc[13]+= pe*k3.y; acc[14] += pe*k3.z; acc[15] += pe*k3.w;
    }
    float sc = SCALE_ / s;
    #pragma unroll
    for (int d = 0; d < 16; d++)
        g_lin[((long)b*HID_ + h*DH_ + dh + d) * N_ + i0 + t] = acc[d] * sc;
}

// =================================================================
// Kernel C v4 (tf32 MMA + cp.async double-buffered pipeline):
//   raw ind (5ch x 32i x 16j) and v (128hd x 16j) stream via cp.async;
//   stage jt+1 in flight while qk-contraction + MMA of stage jt run.
//   grid (32 i, 4 jc, 8 b), 256 thr. dynamic smem 50 KB.
// =================================================================
#define JW    16
#define RAWI_ (5*32*JW)     // 2560 words per buffer
#define VROW_ 20
#define VBUF_ (128*VROW_)   // 2560 words per buffer
#define KC_SMEM ((2*RAWI_ + 2*VBUF_ + 128*VROW_) * 4)   // 51200 B
__global__ void __launch_bounds__(256) kC(const float* __restrict__ ind,
                                          const float* __restrict__ Wind) {
    extern __shared__ unsigned SM[];
    unsigned* rawI0 = SM;
    unsigned* rawI1 = SM + RAWI_;
    unsigned* vb0   = SM + 2*RAWI_;
    unsigned* vb1   = SM + 2*RAWI_ + VBUF_;
    unsigned* qk_s  = SM + 2*RAWI_ + 2*VBUF_;

    int it = blockIdx.x, jchunk = blockIdx.y, b = blockIdx.z;
    int i0 = it * 32, t = threadIdx.x;

    int warp = t >> 5, lane = t & 31;
    int h  = warp >> 1;
    int n0 = (warp & 1) * 16;
    int g  = lane >> 2, tig = lane & 3;

    float w[4][5];
    #pragma unroll
    for (int hh = 0; hh < 4; hh++)
        #pragma unroll
        for (int c = 0; c < 5; c++) w[hh][c] = Wind[hh*INDC_ + c];

    int s_ii = t >> 3, s_j2 = (t & 7) * 2;   // qk contraction map
    const float* indb = ind + ((long)b * INDC_ << 20);
    const float* vbase = g_qkv + ((long)b*QKV_ + 2*HID_) * N_;

    // --- stage issuer: ind 640 float4 + v 512 float4 via cp.async ---
    auto issue = [&](int jt, int bufi) {
        unsigned* rI = bufi ? rawI1 : rawI0;
        unsigned* vB = bufi ? vb1 : vb0;
        int j0 = jchunk * 256 + jt * JW;
        #pragma unroll
        for (int r = 0; r < 2; r++) {
            int f = t + r*256;
            int ch = f >> 7, rem = f & 127, ii = rem >> 2, j4 = (rem & 3) * 4;
            cpa16(&rI[ch*512 + ii*JW + j4],
                  indb + ((long)ch << 20) + (long)(i0 + ii) * N_ + j0 + j4);
        }
        if (t < 128) {
            int f = t + 512;
            int ch = f >> 7, rem = f & 127, ii = rem >> 2, j4 = (rem & 3) * 4;
            cpa16(&rI[ch*512 + ii*JW + j4],
                  indb + ((long)ch << 20) + (long)(i0 + ii) * N_ + j0 + j4);
        }
        #pragma unroll
        for (int r = 0; r < 2; r++) {
            int f = t + r*256;
            int hd = f >> 2, j4 = (f & 3) * 4;
            cpa16(&vB[hd*VROW_ + j4], vbase + (long)hd * N_ + j0 + j4);
        }
        asm volatile("cp.async.commit_group;\n" ::: "memory");
    };

    float acc[2][2][4];
    #pragma unroll
    for (int mt = 0; mt < 2; mt++)
        #pragma unroll
        for (int nt = 0; nt < 2; nt++)
            #pragma unroll
            for (int z = 0; z < 4; z++) acc[mt][nt][z] = 0.f;

    issue(0, 0);

    for (int jt = 0; jt < 16; jt++) {
        int buf = jt & 1;
        unsigned* rI = buf ? rawI1 : rawI0;
        unsigned* vB = buf ? vb1 : vb0;
        __syncthreads();                       // prev MMA done (buffers free)
        if (jt + 1 < 16) {
            issue(jt + 1, buf ^ 1);
            asm volatile("cp.async.wait_group 1;\n" ::: "memory");
        } else {
            asm volatile("cp.async.wait_group 0;\n" ::: "memory");
        }
        __syncthreads();                       // stage jt visible to all

        // qk contraction: raw ind (smem) -> tf32 qk
        {
            float2 iv[5];
            #pragma unroll
            for (int c = 0; c < 5; c++)
                iv[c] = *(const float2*)&rI[c*512 + s_ii*JW + s_j2];
            #pragma unroll
            for (int hh = 0; hh < 4; hh++) {
                float o0 = 0.f, o1 = 0.f;
                #pragma unroll
                for (int c = 0; c < 5; c++) {
                    float wc = w[hh][c];
                    o0 += wc * iv[c].x; o1 += wc * iv[c].y;
                }
                *(uint2*)&qk_s[(hh*32 + s_ii)*VROW_ + s_j2] =
                    make_uint2(tf32u(o0), tf32u(o1));
            }
        }
        __syncthreads();                       // qk ready

        #pragma unroll
        for (int ks = 0; ks < 2; ks++) {
            int k8 = ks * 8;
            unsigned bfr[2][2];
            #pragma unroll
            for (int nt = 0; nt < 2; nt++) {
                int c = h*32 + n0 + nt*8 + g;
                bfr[nt][0] = tf32u(__uint_as_float(vB[c*VROW_ + k8 + tig    ]));
                bfr[nt][1] = tf32u(__uint_as_float(vB[c*VROW_ + k8 + tig + 4]));
            }
            #pragma unroll
            for (int mt = 0; mt < 2; mt++) {
                int r = mt*16 + g;
                unsigned a0 = qk_s[(h*32 + r    )*VROW_ + k8 + tig    ];
                unsigned a1 = qk_s[(h*32 + r + 8)*VROW_ + k8 + tig    ];
                unsigned a2 = qk_s[(h*32 + r    )*VROW_ + k8 + tig + 4];
                unsigned a3 = qk_s[(h*32 + r + 8)*VROW_ + k8 + tig + 4];
                mma8(acc[mt][0], a0, a1, a2, a3, bfr[0][0], bfr[0][1]);
                mma8(acc[mt][1], a0, a1, a2, a3, bfr[1][0], bfr[1][1]);
            }
        }
    }

    // epilogue: overlay SM as [32 i][129] floats, then STG to slab
    __syncthreads();
    float* out_s = (float*)SM;
    #pragma unroll
    for (int mt = 0; mt < 2; mt++) {
        int r = mt*16 + g;
        #pragma unroll
        for (int nt = 0; nt < 2; nt++) {
            int c = h*32 + n0 + nt*8 + tig*2;
            out_s[ r     *129 + c    ] = acc[mt][nt][0];
            out_s[ r     *129 + c + 1] = acc[mt][nt][1];
            out_s[(r + 8)*129 + c    ] = acc[mt][nt][2];
            out_s[(r + 8)*129 + c + 1] = acc[mt][nt][3];
        }
    }
    __syncthreads();
    float* slab = g_o2 + (long)jchunk * SLAB_;
    #pragma unroll
    for (int r2 = 0; r2 < 16; r2++) {
        int idx = t + r2*256, c = idx >> 5, ii = idx & 31;
        long p = ((long)b*HID_ + c) * N_ + i0 + ii;
        slab[p] = out_s[ii*129 + c];
    }
}

// =================================================================
// Kernel DLN (tf32 2-MMA + fused LayerNorm):
//   X = sum of 4 kC slabs + lin;  y = W_out @ X + bias;  LN over o
// =================================================================
__global__ void __launch_bounds__(256) kDLN(const float* __restrict__ W,
                                            const float* __restrict__ bias,
                                            const float* __restrict__ gam,
                                            float* __restrict__ out) {
    int i0 = blockIdx.x * 32, b = blockIdx.y;
    __shared__ unsigned Wsm[16][264];
    __shared__ unsigned Xsm[16][36][2];
    __shared__ float b_s[256], g_s2[256];
    __shared__ float redS[4][32], redQ[4][32];
    __shared__ float mv[32][2];

    int t = threadIdx.x, warp = t >> 5, lane = t & 31;
    int g = lane >> 2, tig = lane & 3;
    int wm = warp >> 1, wn = warp & 1;

    b_s[t] = bias[t];
    g_s2[t] = gam[t];

    int x_k = t >> 4, x_i2 = (t & 15) * 2;

    float acc[4][2][4];
    #pragma unroll
    for (int mt = 0; mt < 4; mt++)
        #pragma unroll
        for (int nt = 0; nt < 2; nt++)
            #pragma unroll
            for (int z = 0; z < 4; z++) acc[mt][nt][z] = 0.f;

    for (int kc = 0; kc < 8; kc++) {
        int k0 = kc * 16;
        __syncthreads();
        #pragma unroll
        for (int q = 0; q < 4; q++) {
            float4 wv = *(const float4*)(W + (long)t * HID_ + k0 + q*4);
            const float* wf = (const float*)&wv;
            #pragma unroll
            for (int j = 0; j < 4; j++) Wsm[q*4+j][t] = tf32u(wf[j]);
        }
        {
            long p = ((long)b*HID_ + k0 + x_k) * N_ + i0 + x_i2;
            float2 s0 = *(const float2*)(g_o2 + p);
            float2 s1 = *(const float2*)(g_o2 + SLAB_ + p);
            float2 s2 = *(const float2*)(g_o2 + 2L*SLAB_ + p);
            float2 s3 = *(const float2*)(g_o2 + 3L*SLAB_ + p);
            float2 l2 = *(const float2*)(g_lin + p);
            float vx = s0.x + s1.x + s2.x + s3.x + l2.x;
            float vy = s0.y + s1.y + s2.y + s3.y + l2.y;
            *(uint2*)&Xsm[x_k][x_i2    ][0] = split_tf32(vx);
            *(uint2*)&Xsm[x_k][x_i2 + 1][0] = split_tf32(vy);
        }
        __syncthreads();
        #pragma unroll
        for (int ks = 0; ks < 2; ks++) {
            int k8 = ks * 8;
            uint2 Bf[2][2];
            #pragma unroll
            for (int nt = 0; nt < 2; nt++) {
                int cn = wn*16 + nt*8 + g;
                Bf[nt][0] = *(uint2*)&Xsm[k8 + tig    ][cn][0];
                Bf[nt][1] = *(uint2*)&Xsm[k8 + tig + 4][cn][0];
            }
            #pragma unroll
            for (int mt = 0; mt < 4; mt++) {
                int rm = (wm*4 + mt)*16 + g;
                unsigned A0 = Wsm[k8 + tig    ][rm    ];
                unsigned A1 = Wsm[k8 + tig    ][rm + 8];
                unsigned A2 = Wsm[k8 + tig + 4][rm    ];
                unsigned A3 = Wsm[k8 + tig + 4][rm + 8];
                #pragma unroll
                for (int nt = 0; nt < 2; nt++) {
                    mma8(acc[mt][nt], A0, A1, A2, A3, Bf[nt][0].x, Bf[nt][1].x);
                    mma8(acc[mt][nt], A0, A1, A2, A3, Bf[nt][0].y, Bf[nt][1].y);
                }
            }
        }
    }

    #pragma unroll
    for (int mt = 0; mt < 4; mt++) {
        int r = (wm*4 + mt)*16 + g;
        float br0 = b_s[r], br8 = b_s[r + 8];
        #pragma unroll
        for (int nt = 0; nt < 2; nt++) {
            acc[mt][nt][0] += br0; acc[mt][nt][1] += br0;
            acc[mt][nt][2] += br8; acc[mt][nt][3] += br8;
        }
    }

    __syncthreads();
    #pragma unroll
    for (int nt = 0; nt < 2; nt++) {
        #pragma unroll
        for (int zz = 0; zz < 2; zz++) {
            float s = 0.f, q = 0.f;
            #pragma unroll
            for (int mt = 0; mt < 4; mt++) {
                float v0 = acc[mt][nt][zz], v8 = acc[mt][nt][zz + 2];
                s += v0 + v8; q += v0*v0 + v8*v8;
            }
            #pragma unroll
            for (int o = 4; o <= 16; o <<= 1) {
                s += __shfl_xor_sync(0xffffffffu, s, o);
                q += __shfl_xor_sync(0xffffffffu, q, o);
            }
            if (g == 0) {
                int cl = wn*16 + nt*8 + tig*2 + zz;
                redS[wm][cl] = s;
                redQ[wm][cl] = q;
            }
        }
    }
    __syncthreads();
    if (t < 32) {
        float s = 0.f, q = 0.f;
        #pragma unroll
        for (int o = 0; o < 4; o++) { s += redS[o][t]; q += redQ[o][t]; }
        float mean = s * (1.f / DIM_);
        float var  = q * (1.f / DIM_) - mean * mean;
        mv[t][0] = mean;
        mv[t][1] = rsqrtf(var + EPS_);
    }
    __syncthreads();

    #pragma unroll
    for (int nt = 0; nt < 2; nt++) {
        int cl = wn*16 + nt*8 + tig*2;
        float m0 = mv[cl][0],  r0 = mv[cl][1];
        float m1 = mv[cl+1][0], r1 = mv[cl+1][1];
        #pragma unroll
        for (int mt = 0; mt < 4; mt++) {
            int r = (wm*4 + mt)*16 + g;
            float ga0 = g_s2[r], ga8 = g_s2[r + 8];
            *(float2*)(out + ((long)b*DIM_ + r) * N_ + i0 + cl) =
                make_float2((acc[mt][nt][0] - m0) * r0 * ga0,
                            (acc[mt][nt][1] - m1) * r1 * ga0);
            *(float2*)(out + ((long)b*DIM_ + r + 8) * N_ + i0 + cl) =
                make_float2((acc[mt][nt][2] - m0) * r0 * ga8,
                            (acc[mt][nt][3] - m1) * r1 * ga8);
        }
    }
}

// =================================================================
extern "C" void kernel_launch(void* const* d_in, const int* in_sizes, int n_in,
                              void* d_out, int out_size) {
    const float* x     = (const float*)d_in[0];
    const float* ind   = (const float*)d_in[1];
    const float* Wqkv  = (const float*)d_in[2];
    const float* Wind  = (const float*)d_in[3];
    const float* Wout  = (const float*)d_in[4];
    const float* bout  = (const float*)d_in[5];
    const float* gam   = (const float*)d_in[6];
    float* out = (float*)d_out;

    static cudaStream_t s1 = nullptr;
    static cudaEvent_t evA = nullptr, evC = nullptr;
    if (!s1) {
        cudaStreamCreateWithFlags(&s1, cudaStreamNonBlocking);
        cudaEventCreateWithFlags(&evA, cudaEventDisableTiming);
        cudaEventCreateWithFlags(&evC, cudaEventDisableTiming);
        cudaFuncSetAttribute(kC, cudaFuncAttributeMaxDynamicSharedMemorySize, KC_SMEM);
    }

    // kernel call order chosen so kC is the 4th kernel (ncu profiles it)
    kA  <<<dim3(16, 3, B_), 256>>>(Wqkv, x);
    cudaEventRecord(evA, 0);

    kK  <<<dim3(HID_, B_), 256>>>();           // also zeroes g_KV
    kKV <<<dim3(B_*H_, 8), 256>>>();

    cudaStreamWaitEvent(s1, evA, 0);
    kC  <<<dim3(32, 4, B_), 256, KC_SMEM, s1>>>(ind, Wind);
    cudaEventRecord(evC, s1);

    kLin<<<dim3(8, 8, B_), 128>>>();

    cudaStreamWaitEvent(0, evC, 0);
    kDLN<<<dim3(32, B_), 256>>>(Wout, bout, gam, out);
}

// round 15
// speedup vs baseline: 1.2293x; 1.2293x over previous
#include <cuda_runtime.h>

#define B_    8
#define N_    1024
#define DIM_  256
#define H_    4
#define DH_   32
#define HID_  128
#define QKV_  384
#define INDC_ 5
#define SCALE_ 0.17677669529663687f
#define EPS_  1e-5f
#define SLAB_ (B_*HID_*N_)

// ---------------- scratch ----------------
__device__ float g_qkv[B_*QKV_*N_];   // q raw, k softmaxed in place, v raw
__device__ float g_KV [B_*H_*DH_*DH_];// KV[b][h][e][d] (atomic accum; zeroed by kK)
__device__ float g_o2 [4*SLAB_];      // indicator-term partials, one slab per j-chunk
__device__ float g_lin[SLAB_];        // linear-term output

__device__ __forceinline__ unsigned tf32u(float f) {
    unsigned u; asm("cvt.rna.tf32.f32 %0, %1;" : "=r"(u) : "f"(f)); return u;
}
__device__ __forceinline__ uint2 split_tf32(float v) {
    unsigned hi = tf32u(v);
    float r = v - __uint_as_float(hi);
    return make_uint2(hi, tf32u(r));
}
__device__ __forceinline__ void mma8(float* c,
                                     unsigned a0, unsigned a1, unsigned a2, unsigned a3,
                                     unsigned b0, unsigned b1) {
    asm volatile("mma.sync.aligned.m16n8k8.row.col.f32.tf32.tf32.f32 "
                 "{%0,%1,%2,%3}, {%4,%5,%6,%7}, {%8,%9}, {%0,%1,%2,%3};\n"
                 : "+f"(c[0]), "+f"(c[1]), "+f"(c[2]), "+f"(c[3])
                 : "r"(a0), "r"(a1), "r"(a2), "r"(a3), "r"(b0), "r"(b1));
}

// =================================================================
// Kernel A (tf32 2-MMA): qkv rows [o_base, o_base+128*gridDim.y)
//   = W_qkv @ x;  D = Wh*xh + Wh*xl
// =================================================================
__global__ void __launch_bounds__(256) kA(const float* __restrict__ W,
                                          const float* __restrict__ x,
                                          int o_base) {
    int i0 = blockIdx.x * 64, o0 = blockIdx.y * 128 + o_base, b = blockIdx.z;
    __shared__ unsigned A_s[16][136];
    __shared__ unsigned B_s[16][68][2];
    int t = threadIdx.x, warp = t >> 5, lane = t & 31;
    int g = lane >> 2, tig = lane & 3;
    int wm = warp >> 1, wn = warp & 1;
    const float* xb = x + (long)b * DIM_ * N_;

    int aq = t & 3, am = t >> 2;
    int bq = t & 15, bk = t >> 4;

    float4 pa[2], pb;
    #pragma unroll
    for (int r = 0; r < 2; r++)
        pa[r] = *(const float4*)(W + (o0 + am + 64*r) * DIM_ + aq*4);
    pb = *(const float4*)(xb + bk * N_ + i0 + bq*4);

    float acc[2][4][4];
    #pragma unroll
    for (int mt = 0; mt < 2; mt++)
        #pragma unroll
        for (int nt = 0; nt < 4; nt++)
            #pragma unroll
            for (int z = 0; z < 4; z++) acc[mt][nt][z] = 0.f;

    for (int c = 0; c < 16; c++) {
        if (c) __syncthreads();
        #pragma unroll
        for (int r = 0; r < 2; r++) {
            const float* pv = (const float*)&pa[r];
            #pragma unroll
            for (int j = 0; j < 4; j++)
                A_s[aq*4+j][am + 64*r] = tf32u(pv[j]);
        }
        {
            const float* pv = (const float*)&pb;
            #pragma unroll
            for (int j = 0; j < 4; j++)
                *(uint2*)&B_s[bk][bq*4+j][0] = split_tf32(pv[j]);
        }
        if (c + 1 < 16) {
            int k0n = (c + 1) * 16;
            #pragma unroll
            for (int r = 0; r < 2; r++)
                pa[r] = *(const float4*)(W + (o0 + am + 64*r) * DIM_ + k0n + aq*4);
            pb = *(const float4*)(xb + (k0n + bk) * N_ + i0 + bq*4);
        }
        __syncthreads();
        #pragma unroll
        for (int ks = 0; ks < 2; ks++) {
            int k8 = ks * 8;
            uint2 Bf[4][2];
            #pragma unroll
            for (int nt = 0; nt < 4; nt++) {
                int cn = wn*32 + nt*8 + g;
                Bf[nt][0] = *(uint2*)&B_s[k8 + tig    ][cn][0];
                Bf[nt][1] = *(uint2*)&B_s[k8 + tig + 4][cn][0];
            }
            #pragma unroll
            for (int mt = 0; mt < 2; mt++) {
                int rm = wm*32 + mt*16 + g;
                unsigned A0 = A_s[k8 + tig    ][rm    ];
                unsigned A1 = A_s[k8 + tig    ][rm + 8];
                unsigned A2 = A_s[k8 + tig + 4][rm    ];
                unsigned A3 = A_s[k8 + tig + 4][rm + 8];
                #pragma unroll
                for (int nt = 0; nt < 4; nt++) {
                    mma8(acc[mt][nt], A0, A1, A2, A3, Bf[nt][0].x, Bf[nt][1].x);
                    mma8(acc[mt][nt], A0, A1, A2, A3, Bf[nt][0].y, Bf[nt][1].y);
                }
            }
        }
    }
    #pragma unroll
    for (int mt = 0; mt < 2; mt++) {
        int row = o0 + wm*32 + mt*16 + g;
        #pragma unroll
        for (int nt = 0; nt < 4; nt++) {
            int col = i0 + wn*32 + nt*8 + tig*2;
            *(float2*)(g_qkv + ((long)b*QKV_ + row    ) * N_ + col) =
                make_float2(acc[mt][nt][0], acc[mt][nt][1]);
            *(float2*)(g_qkv + ((long)b*QKV_ + row + 8) * N_ + col) =
                make_float2(acc[mt][nt][2], acc[mt][nt][3]);
        }
    }
}

// =================================================================
// Kernel K: softmax over n (1024) of each k row, in place.
// Also zeroes g_KV (blocks with row<4; done before kKV runs).
// =================================================================
__global__ void __launch_bounds__(256) kK() {
    int row = blockIdx.x, b = blockIdx.y;
    int t = threadIdx.x;
    if (row < 4) {
        float4 z = make_float4(0.f, 0.f, 0.f, 0.f);
        *(float4*)(g_KV + ((long)(b*4 + row) << 10) + t*4) = z;
    }
    float* p = g_qkv + ((long)b*QKV_ + HID_ + row) * N_;
    __shared__ float red[8];
    float4 v = *(const float4*)(p + t*4);
    float m = fmaxf(fmaxf(v.x, v.y), fmaxf(v.z, v.w));
    #pragma unroll
    for (int o = 16; o; o >>= 1) m = fmaxf(m, __shfl_xor_sync(0xffffffffu, m, o));
    if ((t & 31) == 0) red[t >> 5] = m;
    __syncthreads();
    m = red[0];
    #pragma unroll
    for (int w = 1; w < 8; w++) m = fmaxf(m, red[w]);
    float e0 = __expf(v.x - m), e1 = __expf(v.y - m);
    float e2 = __expf(v.z - m), e3 = __expf(v.w - m);
    float s = e0 + e1 + e2 + e3;
    #pragma unroll
    for (int o = 16; o; o >>= 1) s += __shfl_xor_sync(0xffffffffu, s, o);
    __syncthreads();
    if ((t & 31) == 0) red[t >> 5] = s;
    __syncthreads();
    float tot = 0.f;
    #pragma unroll
    for (int w = 0; w < 8; w++) tot += red[w];
    float inv = 1.f / tot;
    *(float4*)(p + t*4) = make_float4(e0*inv, e1*inv, e2*inv, e3*inv);
}

// =================================================================
// Kernel KV (j-split x8, 4e x 4d tiles): atomic accum into g_KV
// =================================================================
__global__ void __launch_bounds__(256) kKV() {
    int bh = blockIdx.x; int b = bh >> 2, h = bh & 3;
    int jbase = blockIdx.y * 128;
    __shared__ float ksm[32][33], vsm[32][33];
    int t = threadIdx.x;
    int jg = t & 3, dg = (t >> 2) & 7, eg = t >> 5;
    int e0 = eg * 4, d0 = dg * 4;
    float acc[4][4] = {};
    const float* kbase = g_qkv + ((long)b*QKV_ + HID_   + h*DH_) * N_;
    const float* vbase = g_qkv + ((long)b*QKV_ + 2*HID_ + h*DH_) * N_;
    for (int jc = 0; jc < 4; jc++) {
        int j0 = jbase + jc * 32;
        if (jc) __syncthreads();
        {
            int ee = t >> 3, j4 = t & 7;
            float4 kv = *(const float4*)(kbase + ee * N_ + j0 + j4*4);
            ksm[ee][j4*4+0] = kv.x; ksm[ee][j4*4+1] = kv.y;
            ksm[ee][j4*4+2] = kv.z; ksm[ee][j4*4+3] = kv.w;
            float4 vv = *(const float4*)(vbase + ee * N_ + j0 + j4*4);
            vsm[ee][j4*4+0] = vv.x; vsm[ee][j4*4+1] = vv.y;
            vsm[ee][j4*4+2] = vv.z; vsm[ee][j4*4+3] = vv.w;
        }
        __syncthreads();
        #pragma unroll
        for (int i = 0; i < 8; i++) {
            int jj = jg * 8 + ((i + dg) & 7);
            float kr[4], vr[4];
            #pragma unroll
            for (int u = 0; u < 4; u++) kr[u] = ksm[e0+u][jj];
            #pragma unroll
            for (int u = 0; u < 4; u++) vr[u] = vsm[d0+u][jj];
            #pragma unroll
            for (int u = 0; u < 4; u++)
                #pragma unroll
                for (int w2 = 0; w2 < 4; w2++)
                    acc[u][w2] += kr[u] * vr[w2];
        }
    }
    float* dst = g_KV + (long)bh * DH_ * DH_;
    #pragma unroll
    for (int u = 0; u < 4; u++)
        #pragma unroll
        for (int w2 = 0; w2 < 4; w2++)
            atomicAdd(dst + (e0+u)*DH_ + d0 + w2, acc[u][w2]);
}

// =================================================================
// Kernel Lin (fused q-softmax, d-split x2, float4 kv) -> g_lin
// =================================================================
__global__ void __launch_bounds__(128) kLin() {
    int it = blockIdx.x, hy = blockIdx.y, b = blockIdx.z;
    int h = hy >> 1, dh = (hy & 1) * 16;
    int i0 = it * 128, t = threadIdx.x;
    __shared__ float q_s[32][129];
    __shared__ float kv_s[32][20];
    for (int e = 0; e < 32; e++)
        q_s[e][t] = g_qkv[((long)b*QKV_ + h*DH_ + e) * N_ + i0 + t];
    #pragma unroll
    for (int r = 0; r < 4; r++) {
        int idx = t + r * 128;
        int e = idx >> 4, d = idx & 15;
        kv_s[e][d] = g_KV[(((long)(b*H_ + h))*DH_ + e) * DH_ + dh + d];
    }
    __syncthreads();
    float p[32];
    float m = -1e30f;
    #pragma unroll
    for (int e = 0; e < 32; e++) { p[e] = q_s[e][t]; m = fmaxf(m, p[e]); }
    float s = 0.f;
    #pragma unroll
    for (int e = 0; e < 32; e++) { p[e] = __expf(p[e] - m); s += p[e]; }
    float acc[16] = {};
    #pragma unroll 4
    for (int e = 0; e < 32; e++) {
        float pe = p[e];
        float4 k0 = *(float4*)&kv_s[e][0];
        float4 k1 = *(float4*)&kv_s[e][4];
        float4 k2 = *(float4*)&kv_s[e][8];
        float4 k3 = *(float4*)&kv_s[e][12];
        acc[0] += pe*k0.x; acc[1] += pe*k0.y; acc[2]  += pe*k0.z; acc[3]  += pe*k0.w;
        acc[4] += pe*k1.x; acc[5] += pe*k1.y; acc[6]  += pe*k1.z; acc[7]  += pe*k1.w;
        acc[8] += pe*k2.x; acc[9] += pe*k2.y; acc[10] += pe*k2.z; acc[11] += pe*k2.w;
        acc[12]+= pe*k3.x; acc[13]+= pe*k3.y; acc[14] += pe*k3.z; acc[15] += pe*k3.w;
    }
    float sc = SCALE_ / s;
    #pragma unroll
    for (int d = 0; d < 16; d++)
        g_lin[((long)b*HID_ + h*DH_ + dh + d) * N_ + i0 + t] = acc[d] * sc;
}

// =================================================================
// Kernel C v3 (tf32 MMA, wide 32-j stages, all-128-bit staging):
//   n-split warps (acc=16 regs), v staged [hd][j] stride-36 (B direct),
//   no cross-barrier reg prefetch. grid (32 i, 4 jc, 8 b), 256 thr.
//   smem: qk [4*32][36] + v [128][36] = 9216 words = 36 KB.
// =================================================================
#define CW3 36
#define QK3_WORDS (128*CW3)    // 4608
#define SM3_WORDS (QK3_WORDS + 128*CW3)  // 9216
__global__ void __launch_bounds__(256) kC(const float* __restrict__ ind,
                                          const float* __restrict__ Wind) {
    __shared__ unsigned SM[SM3_WORDS];   // 36 KB
    unsigned* qk_s = SM;                 // [h*32+i][CW3]
    unsigned* v_s  = SM + QK3_WORDS;     // [hd][CW3]

    int it = blockIdx.x, jchunk = blockIdx.y, b = blockIdx.z;
    int i0 = it * 32, t = threadIdx.x;

    int warp = t >> 5, lane = t & 31;
    int h  = warp >> 1;
    int n0 = (warp & 1) * 16;
    int g  = lane >> 2, tig = lane & 3;

    float w[4][5];
    #pragma unroll
    for (int hh = 0; hh < 4; hh++)
        #pragma unroll
        for (int c = 0; c < 5; c++) w[hh][c] = Wind[hh*INDC_ + c];

    int s_ii = t >> 3, s_j4 = (t & 7) * 4;   // qk stage: 32 i x 32 j (float4)
    int v_hd = t >> 1, v_js = (t & 1) * 16;  // v stage: 128 hd x 32 j (16 f/thread)
    const float* indb = ind + ((long)b * INDC_ << 20);
    const float* vbase = g_qkv + ((long)b*QKV_ + 2*HID_) * N_;

    float acc[2][2][4];
    #pragma unroll
    for (int mt = 0; mt < 2; mt++)
        #pragma unroll
        for (int nt = 0; nt < 2; nt++)
            #pragma unroll
            for (int z = 0; z < 4; z++) acc[mt][nt][z] = 0.f;

    for (int jt = 0; jt < 8; jt++) {
        int j0 = jchunk * 256 + jt * 32;
        if (jt) __syncthreads();
        // ---- stage qk: 5x LDG.128 -> contraction -> 4x STS.128 ----
        {
            float4 iv[5];
            #pragma unroll
            for (int c = 0; c < 5; c++)
                iv[c] = *(const float4*)(indb + ((long)c << 20) + (long)(i0 + s_ii) * N_ + j0 + s_j4);
            #pragma unroll
            for (int hh = 0; hh < 4; hh++) {
                float o0 = 0.f, o1 = 0.f, o2v = 0.f, o3 = 0.f;
                #pragma unroll
                for (int c = 0; c < 5; c++) {
                    float wc = w[hh][c];
                    o0 += wc * iv[c].x; o1 += wc * iv[c].y;
                    o2v += wc * iv[c].z; o3 += wc * iv[c].w;
                }
                uint4 u4 = make_uint4(tf32u(o0), tf32u(o1), tf32u(o2v), tf32u(o3));
                *(uint4*)&qk_s[(hh*32 + s_ii)*CW3 + s_j4] = u4;
            }
        }
        // ---- stage v: 4x LDG.128 -> cvt -> 4x STS.128 ([hd][j]) ----
        {
            #pragma unroll
            for (int q = 0; q < 4; q++) {
                float4 vv = *(const float4*)(vbase + (long)v_hd * N_ + j0 + v_js + q*4);
                uint4 u4 = make_uint4(tf32u(vv.x), tf32u(vv.y), tf32u(vv.z), tf32u(vv.w));
                *(uint4*)&v_s[v_hd*CW3 + v_js + q*4] = u4;
            }
        }
        __syncthreads();
        // ---- MMA: 4 k-steps of 8 over the 32-j stage ----
        #pragma unroll
        for (int ks = 0; ks < 4; ks++) {
            int k8 = ks * 8;
            unsigned bfr[2][2];
            #pragma unroll
            for (int nt = 0; nt < 2; nt++) {
                int c = h*32 + n0 + nt*8 + g;
                bfr[nt][0] = v_s[c*CW3 + k8 + tig    ];
                bfr[nt][1] = v_s[c*CW3 + k8 + tig + 4];
            }
            #pragma unroll
            for (int mt = 0; mt < 2; mt++) {
                int r = mt*16 + g;
                unsigned a0 = qk_s[(h*32 + r    )*CW3 + k8 + tig    ];
                unsigned a1 = qk_s[(h*32 + r + 8)*CW3 + k8 + tig    ];
                unsigned a2 = qk_s[(h*32 + r    )*CW3 + k8 + tig + 4];
                unsigned a3 = qk_s[(h*32 + r + 8)*CW3 + k8 + tig + 4];
                mma8(acc[mt][0], a0, a1, a2, a3, bfr[0][0], bfr[0][1]);
                mma8(acc[mt][1], a0, a1, a2, a3, bfr[1][0], bfr[1][1]);
            }
        }
    }

    // epilogue: overlay SM as [32 i][129] floats, then STG to slab
    __syncthreads();
    float* out_s = (float*)SM;
    #pragma unroll
    for (int mt = 0; mt < 2; mt++) {
        int r = mt*16 + g;
        #pragma unroll
        for (int nt = 0; nt < 2; nt++) {
            int c = h*32 + n0 + nt*8 + tig*2;
            out_s[ r     *129 + c    ] = acc[mt][nt][0];
            out_s[ r     *129 + c + 1] = acc[mt][nt][1];
            out_s[(r + 8)*129 + c    ] = acc[mt][nt][2];
            out_s[(r + 8)*129 + c + 1] = acc[mt][nt][3];
        }
    }
    __syncthreads();
    float* slab = g_o2 + (long)jchunk * SLAB_;
    #pragma unroll
    for (int r2 = 0; r2 < 16; r2++) {
        int idx = t + r2*256, c = idx >> 5, ii = idx & 31;
        long p = ((long)b*HID_ + c) * N_ + i0 + ii;
        slab[p] = out_s[ii*129 + c];
    }
}

// =================================================================
// Kernel DLN (tf32 2-MMA + fused LayerNorm):
//   X = sum of 4 kC slabs + lin;  y = W_out @ X + bias;  LN over o
// =================================================================
__global__ void __launch_bounds__(256) kDLN(const float* __restrict__ W,
                                            const float* __restrict__ bias,
                                            const float* __restrict__ gam,
                                            float* __restrict__ out) {
    int i0 = blockIdx.x * 32, b = blockIdx.y;
    __shared__ unsigned Wsm[16][264];
    __shared__ unsigned Xsm[16][36][2];
    __shared__ float b_s[256], g_s2[256];
    __shared__ float redS[4][32], redQ[4][32];
    __shared__ float mv[32][2];

    int t = threadIdx.x, warp = t >> 5, lane = t & 31;
    int g = lane >> 2, tig = lane & 3;
    int wm = warp >> 1, wn = warp & 1;

    b_s[t] = bias[t];
    g_s2[t] = gam[t];

    int x_k = t >> 4, x_i2 = (t & 15) * 2;

    float acc[4][2][4];
    #pragma unroll
    for (int mt = 0; mt < 4; mt++)
        #pragma unroll
        for (int nt = 0; nt < 2; nt++)
            #pragma unroll
            for (int z = 0; z < 4; z++) acc[mt][nt][z] = 0.f;

    for (int kc = 0; kc < 8; kc++) {
        int k0 = kc * 16;
        __syncthreads();
        #pragma unroll
        for (int q = 0; q < 4; q++) {
            float4 wv = *(const float4*)(W + (long)t * HID_ + k0 + q*4);
            const float* wf = (const float*)&wv;
            #pragma unroll
            for (int j = 0; j < 4; j++) Wsm[q*4+j][t] = tf32u(wf[j]);
        }
        {
            long p = ((long)b*HID_ + k0 + x_k) * N_ + i0 + x_i2;
            float2 s0 = *(const float2*)(g_o2 + p);
            float2 s1 = *(const float2*)(g_o2 + SLAB_ + p);
            float2 s2 = *(const float2*)(g_o2 + 2L*SLAB_ + p);
            float2 s3 = *(const float2*)(g_o2 + 3L*SLAB_ + p);
            float2 l2 = *(const float2*)(g_lin + p);
            float vx = s0.x + s1.x + s2.x + s3.x + l2.x;
            float vy = s0.y + s1.y + s2.y + s3.y + l2.y;
            *(uint2*)&Xsm[x_k][x_i2    ][0] = split_tf32(vx);
            *(uint2*)&Xsm[x_k][x_i2 + 1][0] = split_tf32(vy);
        }
        __syncthreads();
        #pragma unroll
        for (int ks = 0; ks < 2; ks++) {
            int k8 = ks * 8;
            uint2 Bf[2][2];
            #pragma unroll
            for (int nt = 0; nt < 2; nt++) {
                int cn = wn*16 + nt*8 + g;
                Bf[nt][0] = *(uint2*)&Xsm[k8 + tig    ][cn][0];
                Bf[nt][1] = *(uint2*)&Xsm[k8 + tig + 4][cn][0];
            }
            #pragma unroll
            for (int mt = 0; mt < 4; mt++) {
                int rm = (wm*4 + mt)*16 + g;
                unsigned A0 = Wsm[k8 + tig    ][rm    ];
                unsigned A1 = Wsm[k8 + tig    ][rm + 8];
                unsigned A2 = Wsm[k8 + tig + 4][rm    ];
                unsigned A3 = Wsm[k8 + tig + 4][rm + 8];
                #pragma unroll
                for (int nt = 0; nt < 2; nt++) {
                    mma8(acc[mt][nt], A0, A1, A2, A3, Bf[nt][0].x, Bf[nt][1].x);
                    mma8(acc[mt][nt], A0, A1, A2, A3, Bf[nt][0].y, Bf[nt][1].y);
                }
            }
        }
    }

    #pragma unroll
    for (int mt = 0; mt < 4; mt++) {
        int r = (wm*4 + mt)*16 + g;
        float br0 = b_s[r], br8 = b_s[r + 8];
        #pragma unroll
        for (int nt = 0; nt < 2; nt++) {
            acc[mt][nt][0] += br0; acc[mt][nt][1] += br0;
            acc[mt][nt][2] += br8; acc[mt][nt][3] += br8;
        }
    }

    __syncthreads();
    #pragma unroll
    for (int nt = 0; nt < 2; nt++) {
        #pragma unroll
        for (int zz = 0; zz < 2; zz++) {
            float s = 0.f, q = 0.f;
            #pragma unroll
            for (int mt = 0; mt < 4; mt++) {
                float v0 = acc[mt][nt][zz], v8 = acc[mt][nt][zz + 2];
                s += v0 + v8; q += v0*v0 + v8*v8;
            }
            #pragma unroll
            for (int o = 4; o <= 16; o <<= 1) {
                s += __shfl_xor_sync(0xffffffffu, s, o);
                q += __shfl_xor_sync(0xffffffffu, q, o);
            }
            if (g == 0) {
                int cl = wn*16 + nt*8 + tig*2 + zz;
                redS[wm][cl] = s;
                redQ[wm][cl] = q;
            }
        }
    }
    __syncthreads();
    if (t < 32) {
        float s = 0.f, q = 0.f;
        #pragma unroll
        for (int o = 0; o < 4; o++) { s += redS[o][t]; q += redQ[o][t]; }
        float mean = s * (1.f / DIM_);
        float var  = q * (1.f / DIM_) - mean * mean;
        mv[t][0] = mean;
        mv[t][1] = rsqrtf(var + EPS_);
    }
    __syncthreads();

    #pragma unroll
    for (int nt = 0; nt < 2; nt++) {
        int cl = wn*16 + nt*8 + tig*2;
        float m0 = mv[cl][0],  r0 = mv[cl][1];
        float m1 = mv[cl+1][0], r1 = mv[cl+1][1];
        #pragma unroll
        for (int mt = 0; mt < 4; mt++) {
            int r = (wm*4 + mt)*16 + g;
            float ga0 = g_s2[r], ga8 = g_s2[r + 8];
            *(float2*)(out + ((long)b*DIM_ + r) * N_ + i0 + cl) =
                make_float2((acc[mt][nt][0] - m0) * r0 * ga0,
                            (acc[mt][nt][1] - m1) * r1 * ga0);
            *(float2*)(out + ((long)b*DIM_ + r + 8) * N_ + i0 + cl) =
                make_float2((acc[mt][nt][2] - m0) * r0 * ga8,
                            (acc[mt][nt][3] - m1) * r1 * ga8);
        }
    }
}

// =================================================================
extern "C" void kernel_launch(void* const* d_in, const int* in_sizes, int n_in,
                              void* d_out, int out_size) {
    const float* x     = (const float*)d_in[0];
    const float* ind   = (const float*)d_in[1];
    const float* Wqkv  = (const float*)d_in[2];
    const float* Wind  = (const float*)d_in[3];
    const float* Wout  = (const float*)d_in[4];
    const float* bout  = (const float*)d_in[5];
    const float* gam   = (const float*)d_in[6];
    float* out = (float*)d_out;

    static cudaStream_t s1 = nullptr;
    static cudaEvent_t evV = nullptr, evC = nullptr;
    if (!s1) {
        cudaStreamCreateWithFlags(&s1, cudaStreamNonBlocking);
        cudaEventCreateWithFlags(&evV, cudaEventDisableTiming);
        cudaEventCreateWithFlags(&evC, cudaEventDisableTiming);
    }

    // v-rows first so kC can start while q,k are still being computed.
    kA<<<dim3(16, 1, B_), 256>>>(Wqkv, x, 2*HID_);    // v only (rows 256..383)
    cudaEventRecord(evV, 0);

    kA<<<dim3(16, 2, B_), 256>>>(Wqkv, x, 0);         // q,k (rows 0..255)
    kK<<<dim3(HID_, B_), 256>>>();                     // also zeroes g_KV

    cudaStreamWaitEvent(s1, evV, 0);
    kC<<<dim3(32, 4, B_), 256, 0, s1>>>(ind, Wind);    // 4th launch (ncu)
    cudaEventRecord(evC, s1);

    kKV<<<dim3(B_*H_, 8), 256>>>();
    kLin<<<dim3(8, 8, B_), 128>>>();

    cudaStreamWaitEvent(0, evC, 0);
    kDLN<<<dim3(32, B_), 256>>>(Wout, bout, gam, out);
}